// round 16
// baseline (speedup 1.0000x reference)
#include <cuda_runtime.h>
#include <cuda_fp16.h>
#include <math.h>
#include <stdint.h>

#define NN 10000
#define NE 160000

// ---- scratch (static device globals; zero-initialized at module load) ----
__device__ float g_deg[NN];
__device__ float g_dis[NN];
__device__ int   g_cnt[NN];
__device__ int   g_rowptr[NN + 1];
__device__ int   g_cursor[NN];
__device__ int   g_csr_src[NE];
__device__ float g_csr_w[NE];
__device__ float g_tx1[NN * 128];            // fp32 tx1 (L1 prop2 input)
__device__ __half g_xh1[NN * 128];           // L1 output fp16 (L2 prop input)
__device__ __half g_xh[NN * 256];            // L2 output fp16 (L3 prop input)
__device__ __half g_tx1h[NN * 256];          // fp16 tx1 (L2 uses stride 128, L3 stride 256)
__device__ __half g_Abig[NN * 1536];         // GEMM A rows (max 768 used now... keep size)
__device__ __half g_Ah[NN * 512];            // head A (hi-only, from L3 epilogue)
// B stored deduplicated: single hi copy of length K per output row
__device__ __half g_B1[128 * 384];
__device__ __half g_B2[256 * 384];
__device__ __half g_B3[512 * 768];
__device__ __half g_Bh[512 * 512];           // [mu(256 rows) | std(256 rows)], K=512

__device__ __forceinline__ uint32_t smem_u32(const void* p) {
    uint32_t a;
    asm("{ .reg .u64 t; cvta.to.shared.u64 t, %1; cvt.u32.u64 %0, t; }" : "=r"(a) : "l"(p));
    return a;
}
__device__ __forceinline__ uint32_t pack_h2(float a, float b) {
    __half2 t = __floats2half2_rn(a, b);
    return *(uint32_t*)&t;
}

// =============== graph preprocessing ===============
__global__ void k_counts(const int* __restrict__ ei, float* __restrict__ deg,
                         int* __restrict__ cnt) {
    int e = blockIdx.x * blockDim.x + threadIdx.x;
    if (e < NE) {
        atomicAdd(&deg[ei[e]], 1.f);
        atomicAdd(&cnt[ei[NE + e]], 1);
    }
}
// scan cnt -> rowptr/cursor; computes dis; re-zeroes cnt/deg for next call
__global__ void k_scan(int* __restrict__ cnt, int* __restrict__ rowptr,
                       int* __restrict__ cursor, float* __restrict__ deg,
                       float* __restrict__ dis) {
    __shared__ int wsum[32];
    __shared__ int carry_s;
    int tid = threadIdx.x, lane = tid & 31, wid = tid >> 5;
    if (tid == 0) { carry_s = 0; rowptr[0] = 0; }
    __syncthreads();
    for (int base = 0; base < NN; base += 1024) {
        int i = base + tid;
        int v = 0;
        if (i < NN) {
            float d = deg[i];
            dis[i] = (d > 0.f) ? rsqrtf(d) : 0.f;
            deg[i] = 0.f;                    // re-zero for next call
            v = cnt[i];
            cnt[i] = 0;                      // re-zero for next call
        }
        int x = v;
#pragma unroll
        for (int o = 1; o < 32; o <<= 1) {
            int t = __shfl_up_sync(0xffffffffu, x, o);
            if (lane >= o) x += t;
        }
        if (lane == 31) wsum[wid] = x;
        __syncthreads();
        if (wid == 0) {
            int s = wsum[lane];
#pragma unroll
            for (int o = 1; o < 32; o <<= 1) {
                int t = __shfl_up_sync(0xffffffffu, s, o);
                if (lane >= o) s += t;
            }
            wsum[lane] = s;
        }
        __syncthreads();
        int inc = carry_s + ((wid > 0) ? wsum[wid - 1] : 0) + x;
        if (i < NN) { rowptr[i + 1] = inc; cursor[i] = inc - v; }
        __syncthreads();
        if (tid == 1023) carry_s = inc;
        __syncthreads();
    }
}
__global__ void k_scatter(const int* __restrict__ ei, const float* __restrict__ dis,
                          int* __restrict__ cursor, int* __restrict__ csr_src,
                          float* __restrict__ csr_w) {
    int e = blockIdx.x * blockDim.x + threadIdx.x;
    if (e < NE) {
        int r = ei[e];
        int c = ei[NE + e];
        int p = atomicAdd(&cursor[c], 1);
        csr_src[p] = r;
        csr_w[p] = -dis[r] * dis[c];
    }
}

// =============== fp32-gather props (L1, Fin=128, 2-term writes) ===============
__device__ __forceinline__ void split_write4(__half* row, int Fin, int pos, float4 v) {
    float hx = __half2float(__float2half_rn(v.x));
    float hy = __half2float(__float2half_rn(v.y));
    float hz = __half2float(__float2half_rn(v.z));
    float hw = __half2float(__float2half_rn(v.w));
    uint2 hi = make_uint2(pack_h2(v.x, v.y), pack_h2(v.z, v.w));
    uint2 lo = make_uint2(pack_h2(v.x - hx, v.y - hy), pack_h2(v.z - hz, v.w - hw));
    *(uint2*)(row + pos) = hi;
    *(uint2*)(row + 3 * Fin + pos) = lo;
}
__device__ __forceinline__ float4 gather_acc(
    const int* __restrict__ csr_src, const float* __restrict__ csr_w,
    const float* __restrict__ base, int Fin, int f, int s, int e, int lane)
{
    float4 a0 = make_float4(0.f, 0.f, 0.f, 0.f);
    float4 a1 = a0, a2 = a0, a3 = a0;
    for (int j0 = s; j0 < e; j0 += 32) {
        int j = j0 + lane;
        int es = 0; float ew = 0.f;
        if (j < e) { es = csr_src[j]; ew = csr_w[j]; }
        int m = min(32, e - j0);
        int t = 0;
        for (; t + 4 <= m; t += 4) {
            int s0 = __shfl_sync(0xffffffffu, es, t + 0);
            int s1 = __shfl_sync(0xffffffffu, es, t + 1);
            int s2 = __shfl_sync(0xffffffffu, es, t + 2);
            int s3 = __shfl_sync(0xffffffffu, es, t + 3);
            float w0 = __shfl_sync(0xffffffffu, ew, t + 0);
            float w1 = __shfl_sync(0xffffffffu, ew, t + 1);
            float w2 = __shfl_sync(0xffffffffu, ew, t + 2);
            float w3 = __shfl_sync(0xffffffffu, ew, t + 3);
            float4 v0 = *(const float4*)(base + (size_t)s0 * Fin + f);
            float4 v1 = *(const float4*)(base + (size_t)s1 * Fin + f);
            float4 v2 = *(const float4*)(base + (size_t)s2 * Fin + f);
            float4 v3 = *(const float4*)(base + (size_t)s3 * Fin + f);
            a0.x += w0 * v0.x; a0.y += w0 * v0.y; a0.z += w0 * v0.z; a0.w += w0 * v0.w;
            a1.x += w1 * v1.x; a1.y += w1 * v1.y; a1.z += w1 * v1.z; a1.w += w1 * v1.w;
            a2.x += w2 * v2.x; a2.y += w2 * v2.y; a2.z += w2 * v2.z; a2.w += w2 * v2.w;
            a3.x += w3 * v3.x; a3.y += w3 * v3.y; a3.z += w3 * v3.z; a3.w += w3 * v3.w;
        }
        for (; t < m; t++) {
            int s0 = __shfl_sync(0xffffffffu, es, t);
            float w0 = __shfl_sync(0xffffffffu, ew, t);
            float4 v0 = *(const float4*)(base + (size_t)s0 * Fin + f);
            a0.x += w0 * v0.x; a0.y += w0 * v0.y; a0.z += w0 * v0.z; a0.w += w0 * v0.w;
        }
    }
    a0.x += a1.x + a2.x + a3.x;
    a0.y += a1.y + a2.y + a3.y;
    a0.z += a1.z + a2.z + a3.z;
    a0.w += a1.w + a2.w + a3.w;
    return a0;
}
__global__ __launch_bounds__(128) void k_gprop1(
    const int* __restrict__ rowptr, const int* __restrict__ csr_src,
    const float* __restrict__ csr_w, const float* __restrict__ x,
    float* __restrict__ tx1, __half* __restrict__ Abig)
{
    const int Fin = 128;
    int warp = threadIdx.x >> 5, lane = threadIdx.x & 31;
    int n = blockIdx.x * 4 + warp;
    if (n >= NN) return;
    int f = lane * 4;
    float4 acc = gather_acc(csr_src, csr_w, x, Fin, f, rowptr[n], rowptr[n + 1], lane);
    float4 x0 = *(const float4*)(x + (size_t)n * Fin + f);
    __half* row = Abig + (size_t)n * 6 * Fin;
    split_write4(row, Fin, f, x0);
    split_write4(row, Fin, Fin + f, acc);
    *(float4*)(tx1 + (size_t)n * Fin + f) = acc;
}
__global__ __launch_bounds__(128) void k_gprop2(
    const int* __restrict__ rowptr, const int* __restrict__ csr_src,
    const float* __restrict__ csr_w, const float* __restrict__ x,
    const float* __restrict__ tx1, __half* __restrict__ Abig)
{
    const int Fin = 128;
    int warp = threadIdx.x >> 5, lane = threadIdx.x & 31;
    int n = blockIdx.x * 4 + warp;
    if (n >= NN) return;
    int f = lane * 4;
    float4 acc = gather_acc(csr_src, csr_w, tx1, Fin, f, rowptr[n], rowptr[n + 1], lane);
    float4 x0 = *(const float4*)(x + (size_t)n * Fin + f);
    float4 t2 = make_float4(2.f * acc.x - x0.x, 2.f * acc.y - x0.y,
                            2.f * acc.z - x0.z, 2.f * acc.w - x0.w);
    __half* row = Abig + (size_t)n * 6 * Fin;
    split_write4(row, Fin, 2 * Fin + f, t2);
}

// =============== fp16-gather props, Fin=128 (L2, 2-term A writes) ===============
__device__ __forceinline__ void h4_acc(float* acc, uint2 v, float w) {
    const __half2* h = (const __half2*)&v;
    float2 a = __half22float2(h[0]);
    float2 b = __half22float2(h[1]);
    acc[0] += w * a.x; acc[1] += w * a.y;
    acc[2] += w * b.x; acc[3] += w * b.y;
}
__device__ __forceinline__ void gather_acc_h128(
    float* acc, const int* __restrict__ csr_src, const float* __restrict__ csr_w,
    const __half* __restrict__ base, int f, int s, int e, int lane)
{
    for (int j0 = s; j0 < e; j0 += 32) {
        int j = j0 + lane;
        int es = 0; float ew = 0.f;
        if (j < e) { es = csr_src[j]; ew = csr_w[j]; }
        int m = min(32, e - j0);
        int t = 0;
        for (; t + 4 <= m; t += 4) {
            int s0 = __shfl_sync(0xffffffffu, es, t + 0);
            int s1 = __shfl_sync(0xffffffffu, es, t + 1);
            int s2 = __shfl_sync(0xffffffffu, es, t + 2);
            int s3 = __shfl_sync(0xffffffffu, es, t + 3);
            float w0 = __shfl_sync(0xffffffffu, ew, t + 0);
            float w1 = __shfl_sync(0xffffffffu, ew, t + 1);
            float w2 = __shfl_sync(0xffffffffu, ew, t + 2);
            float w3 = __shfl_sync(0xffffffffu, ew, t + 3);
            uint2 v0 = *(const uint2*)(base + (size_t)s0 * 128 + f);
            uint2 v1 = *(const uint2*)(base + (size_t)s1 * 128 + f);
            uint2 v2 = *(const uint2*)(base + (size_t)s2 * 128 + f);
            uint2 v3 = *(const uint2*)(base + (size_t)s3 * 128 + f);
            h4_acc(acc, v0, w0);
            h4_acc(acc, v1, w1);
            h4_acc(acc, v2, w2);
            h4_acc(acc, v3, w3);
        }
        for (; t < m; t++) {
            int s0 = __shfl_sync(0xffffffffu, es, t);
            float w0 = __shfl_sync(0xffffffffu, ew, t);
            uint2 v0 = *(const uint2*)(base + (size_t)s0 * 128 + f);
            h4_acc(acc, v0, w0);
        }
    }
}
__device__ __forceinline__ void split_pair(float a, float b, uint32_t& hi, uint32_t& lo) {
    float ha = __half2float(__float2half_rn(a));
    float hb = __half2float(__float2half_rn(b));
    hi = pack_h2(a, b);
    lo = pack_h2(a - ha, b - hb);
}
// prop1 (L2): A row stride 768 = [hi0 hi1 hi2 | lo0 lo1 lo2]; lo0 = 0 (x already fp16)
__global__ __launch_bounds__(128) void k_gprop1h128(
    const int* __restrict__ rowptr, const int* __restrict__ csr_src,
    const float* __restrict__ csr_w, const __half* __restrict__ xh,
    __half* __restrict__ tx1h, __half* __restrict__ Abig)
{
    int warp = threadIdx.x >> 5, lane = threadIdx.x & 31;
    int n = blockIdx.x * 4 + warp;
    if (n >= NN) return;
    int f = lane * 4;
    float acc[4] = {0.f, 0.f, 0.f, 0.f};
    gather_acc_h128(acc, csr_src, csr_w, xh, f, rowptr[n], rowptr[n + 1], lane);
    uint2 x0 = *(const uint2*)(xh + (size_t)n * 128 + f);
    __half* row = Abig + (size_t)n * 768;
    *(uint2*)(row + f) = x0;                             // hi tx0 (exact)
    *(uint2*)(row + 384 + f) = make_uint2(0u, 0u);       // lo tx0 = 0
    uint2 hi, lo;
    split_pair(acc[0], acc[1], hi.x, lo.x);
    split_pair(acc[2], acc[3], hi.y, lo.y);
    *(uint2*)(row + 128 + f) = hi;                       // hi tx1
    *(uint2*)(row + 512 + f) = lo;                       // lo tx1
    *(uint2*)(tx1h + (size_t)n * 128 + f) = hi;          // fp16 tx1 table for prop2
}
__global__ __launch_bounds__(128) void k_gprop2h128(
    const int* __restrict__ rowptr, const int* __restrict__ csr_src,
    const float* __restrict__ csr_w, const __half* __restrict__ xh,
    const __half* __restrict__ tx1h, __half* __restrict__ Abig)
{
    int warp = threadIdx.x >> 5, lane = threadIdx.x & 31;
    int n = blockIdx.x * 4 + warp;
    if (n >= NN) return;
    int f = lane * 4;
    float acc[4] = {0.f, 0.f, 0.f, 0.f};
    gather_acc_h128(acc, csr_src, csr_w, tx1h, f, rowptr[n], rowptr[n + 1], lane);
    uint2 x0 = *(const uint2*)(xh + (size_t)n * 128 + f);
    const __half2* xh2 = (const __half2*)&x0;
    float2 fa = __half22float2(xh2[0]);
    float2 fb = __half22float2(xh2[1]);
    float t2[4] = {2.f * acc[0] - fa.x, 2.f * acc[1] - fa.y,
                   2.f * acc[2] - fb.x, 2.f * acc[3] - fb.y};
    __half* row = Abig + (size_t)n * 768;
    uint2 hi, lo;
    split_pair(t2[0], t2[1], hi.x, lo.x);
    split_pair(t2[2], t2[3], hi.y, lo.y);
    *(uint2*)(row + 256 + f) = hi;                       // hi tx2
    *(uint2*)(row + 640 + f) = lo;                       // lo tx2
}

// =============== fp16-gather props, Fin=256 (L3, hi-only writes) ===============
__device__ __forceinline__ void h8_acc(float* acc, uint4 v, float w) {
    const __half2* h = (const __half2*)&v;
#pragma unroll
    for (int q = 0; q < 4; q++) {
        float2 fv = __half22float2(h[q]);
        acc[2 * q]     += w * fv.x;
        acc[2 * q + 1] += w * fv.y;
    }
}
__device__ __forceinline__ void gather_acc_h(
    float* acc, const int* __restrict__ csr_src, const float* __restrict__ csr_w,
    const __half* __restrict__ base, int f, int s, int e, int lane)
{
    for (int j0 = s; j0 < e; j0 += 32) {
        int j = j0 + lane;
        int es = 0; float ew = 0.f;
        if (j < e) { es = csr_src[j]; ew = csr_w[j]; }
        int m = min(32, e - j0);
        int t = 0;
        for (; t + 4 <= m; t += 4) {
            int s0 = __shfl_sync(0xffffffffu, es, t + 0);
            int s1 = __shfl_sync(0xffffffffu, es, t + 1);
            int s2 = __shfl_sync(0xffffffffu, es, t + 2);
            int s3 = __shfl_sync(0xffffffffu, es, t + 3);
            float w0 = __shfl_sync(0xffffffffu, ew, t + 0);
            float w1 = __shfl_sync(0xffffffffu, ew, t + 1);
            float w2 = __shfl_sync(0xffffffffu, ew, t + 2);
            float w3 = __shfl_sync(0xffffffffu, ew, t + 3);
            uint4 v0 = *(const uint4*)(base + (size_t)s0 * 256 + f);
            uint4 v1 = *(const uint4*)(base + (size_t)s1 * 256 + f);
            uint4 v2 = *(const uint4*)(base + (size_t)s2 * 256 + f);
            uint4 v3 = *(const uint4*)(base + (size_t)s3 * 256 + f);
            h8_acc(acc, v0, w0);
            h8_acc(acc, v1, w1);
            h8_acc(acc, v2, w2);
            h8_acc(acc, v3, w3);
        }
        for (; t < m; t++) {
            int s0 = __shfl_sync(0xffffffffu, es, t);
            float w0 = __shfl_sync(0xffffffffu, ew, t);
            uint4 v0 = *(const uint4*)(base + (size_t)s0 * 256 + f);
            h8_acc(acc, v0, w0);
        }
    }
}
__device__ __forceinline__ uint4 pack_h8(const float* a) {
    uint4 r;
    r.x = pack_h2(a[0], a[1]);
    r.y = pack_h2(a[2], a[3]);
    r.z = pack_h2(a[4], a[5]);
    r.w = pack_h2(a[6], a[7]);
    return r;
}
__global__ __launch_bounds__(128) void k_gprop1h(
    const int* __restrict__ rowptr, const int* __restrict__ csr_src,
    const float* __restrict__ csr_w, const __half* __restrict__ xh,
    __half* __restrict__ tx1h, __half* __restrict__ Abig)
{
    int warp = threadIdx.x >> 5, lane = threadIdx.x & 31;
    int n = blockIdx.x * 4 + warp;
    if (n >= NN) return;
    int f = lane * 8;
    float acc[8] = {0.f, 0.f, 0.f, 0.f, 0.f, 0.f, 0.f, 0.f};
    gather_acc_h(acc, csr_src, csr_w, xh, f, rowptr[n], rowptr[n + 1], lane);
    uint4 x0 = *(const uint4*)(xh + (size_t)n * 256 + f);
    __half* row = Abig + (size_t)n * 768;
    *(uint4*)(row + f) = x0;
    uint4 p = pack_h8(acc);
    *(uint4*)(row + 256 + f) = p;
    *(uint4*)(tx1h + (size_t)n * 256 + f) = p;
}
__global__ __launch_bounds__(128) void k_gprop2h(
    const int* __restrict__ rowptr, const int* __restrict__ csr_src,
    const float* __restrict__ csr_w, const __half* __restrict__ xh,
    const __half* __restrict__ tx1h, __half* __restrict__ Abig)
{
    int warp = threadIdx.x >> 5, lane = threadIdx.x & 31;
    int n = blockIdx.x * 4 + warp;
    if (n >= NN) return;
    int f = lane * 8;
    float acc[8] = {0.f, 0.f, 0.f, 0.f, 0.f, 0.f, 0.f, 0.f};
    gather_acc_h(acc, csr_src, csr_w, tx1h, f, rowptr[n], rowptr[n + 1], lane);
    uint4 x0 = *(const uint4*)(xh + (size_t)n * 256 + f);
    const __half2* xh2 = (const __half2*)&x0;
    float t2[8];
#pragma unroll
    for (int q = 0; q < 4; q++) {
        float2 fv = __half22float2(xh2[q]);
        t2[2 * q]     = 2.f * acc[2 * q]     - fv.x;
        t2[2 * q + 1] = 2.f * acc[2 * q + 1] - fv.y;
    }
    *(uint4*)(Abig + (size_t)n * 768 + 512 + f) = pack_h8(t2);
}

// =============== single mega weight-conversion kernel (all 5 matrices) ===============
__global__ void k_wconv_all(
    const float* __restrict__ W1, const float* __restrict__ W2,
    const float* __restrict__ W3, const float* __restrict__ Wmu,
    const float* __restrict__ Wstd,
    __half* __restrict__ B1, __half* __restrict__ B2,
    __half* __restrict__ B3, __half* __restrict__ Bh)
{
    int b = blockIdx.x;
    const float* W; __half* B; int K, N;
    if (b < 192)       { W = W1;   B = B1;                        K = 384; N = 128; }
    else if (b < 576)  { W = W2;   B = B2;                        K = 384; N = 256; b -= 192; }
    else if (b < 2112) { W = W3;   B = B3;                        K = 768; N = 512; b -= 576; }
    else if (b < 2624) { W = Wmu;  B = Bh;                        K = 512; N = 256; b -= 2112; }
    else               { W = Wstd; B = Bh + (size_t)256 * 512;    K = 512; N = 256; b -= 2624; }
    int i = b * 256 + threadIdx.x;
    if (i < K * N) {
        int k = i / N;
        int n = i - k * N;
        B[(size_t)n * K + k] = __float2half_rn(W[i]);
    }
}

// =============== mma.sync fp16 GEMM, 64x128 tile, BK=64, 4-stage cp.async ===============
#define LDT 72
#define NSTAGE 4
#define A_ELEMS (64 * LDT)
#define B_ELEMS (128 * LDT)

__device__ __forceinline__ void ldm_x4(uint32_t& r0, uint32_t& r1, uint32_t& r2, uint32_t& r3,
                                       uint32_t a) {
    asm volatile("ldmatrix.sync.aligned.m8n8.x4.shared.b16 {%0,%1,%2,%3}, [%4];"
                 : "=r"(r0), "=r"(r1), "=r"(r2), "=r"(r3) : "r"(a));
}
__device__ __forceinline__ void mma_f16(float* c, const uint32_t* a, const uint32_t* b) {
    asm volatile(
        "mma.sync.aligned.m16n8k16.row.col.f32.f16.f16.f32 "
        "{%0,%1,%2,%3}, {%4,%5,%6,%7}, {%8,%9}, {%0,%1,%2,%3};"
        : "+f"(c[0]), "+f"(c[1]), "+f"(c[2]), "+f"(c[3])
        : "r"(a[0]), "r"(a[1]), "r"(a[2]), "r"(a[3]), "r"(b[0]), "r"(b[1]));
}
__device__ __forceinline__ void cp16(uint32_t dst, const void* src, int pred16) {
    asm volatile("cp.async.cg.shared.global [%0], [%1], 16, %2;"
                 :: "r"(dst), "l"(src), "r"(pred16) : "memory");
}

// Asplit != 0: write single hi fp16 row (len ldc) instead of fp32 C.
__global__ __launch_bounds__(256) void k_mgemm(
    const __half* __restrict__ A, const __half* __restrict__ B,
    const float* __restrict__ bias0, const float* __restrict__ bias1,
    float* __restrict__ C0, float* __restrict__ C1,
    __half* __restrict__ Asplit,
    int M, int Kbig, int Kb, int ldc, int relu, int split)
{
    extern __shared__ __align__(16) __half smp[];
    __half* sAp = smp;
    __half* sBp = smp + NSTAGE * A_ELEMS;

    const int tid = threadIdx.x;
    const int wid = tid >> 5;
    const int lane = tid & 31;
    const int bm = blockIdx.y * 64;
    const int bn = blockIdx.x * 128;
    const int warp_m = (wid & 1) * 32;
    const int warp_n = (wid >> 1) * 32;

    float acc[2][4][4];
#pragma unroll
    for (int i = 0; i < 2; i++)
#pragma unroll
        for (int j = 0; j < 4; j++)
#pragma unroll
            for (int q = 0; q < 4; q++) acc[i][j][q] = 0.f;

    uint32_t sA_u[NSTAGE], sB_u[NSTAGE];
#pragma unroll
    for (int s = 0; s < NSTAGE; s++) {
        sA_u[s] = smem_u32(sAp + s * A_ELEMS);
        sB_u[s] = smem_u32(sBp + s * B_ELEMS);
    }
    const int niter = Kbig >> 6;

    auto issue = [&](int stage, int k0) {
#pragma unroll
        for (int h = 0; h < 2; h++) {
            int c = tid + h * 256;
            int r = c >> 3, col = c & 7;
            cp16(sA_u[stage] + (r * LDT + col * 8) * 2,
                 A + (size_t)(bm + r) * Kbig + k0 + col * 8, (bm + r) < M ? 16 : 0);
        }
        int kb = (k0 < Kb) ? k0 : k0 - Kb;
#pragma unroll
        for (int h = 0; h < 4; h++) {
            int c = tid + h * 256;
            int r = c >> 3, col = c & 7;
            cp16(sB_u[stage] + (r * LDT + col * 8) * 2,
                 B + (size_t)(bn + r) * Kb + kb + col * 8, 16);
        }
        asm volatile("cp.async.commit_group;" ::: "memory");
    };

    issue(0, 0);
    issue(1, 64);
    issue(2, 128);

    int stage = 0;
    for (int it = 0; it < niter; it++) {
        const int ahead = niter - 1 - it;
        if (ahead >= 2)      asm volatile("cp.async.wait_group 2;" ::: "memory");
        else if (ahead == 1) asm volatile("cp.async.wait_group 1;" ::: "memory");
        else                 asm volatile("cp.async.wait_group 0;" ::: "memory");
        __syncthreads();

        if (it + 3 < niter) {
            int ns = stage + 3; if (ns >= NSTAGE) ns -= NSTAGE;
            issue(ns, (it + 3) << 6);
        }

#pragma unroll
        for (int ks = 0; ks < 4; ks++) {
            uint32_t af[2][4];
            uint32_t bf[4][2];
#pragma unroll
            for (int mf = 0; mf < 2; mf++) {
                uint32_t addr = sA_u[stage] +
                    ((warp_m + mf * 16 + (lane & 15)) * LDT + ks * 16 + (lane >> 4) * 8) * 2;
                ldm_x4(af[mf][0], af[mf][1], af[mf][2], af[mf][3], addr);
            }
#pragma unroll
            for (int nfp = 0; nfp < 2; nfp++) {
                uint32_t addr = sB_u[stage] +
                    ((warp_n + nfp * 16 + (lane & 15)) * LDT + ks * 16 + (lane >> 4) * 8) * 2;
                uint32_t r0, r1, r2, r3;
                ldm_x4(r0, r1, r2, r3, addr);
                bf[nfp * 2 + 0][0] = r0; bf[nfp * 2 + 1][0] = r1;
                bf[nfp * 2 + 0][1] = r2; bf[nfp * 2 + 1][1] = r3;
            }
#pragma unroll
            for (int mf = 0; mf < 2; mf++)
#pragma unroll
                for (int nf = 0; nf < 4; nf++)
                    mma_f16(acc[mf][nf], af[mf], bf[nf]);
        }
        if (++stage == NSTAGE) stage = 0;
    }

    // epilogue
#pragma unroll
    for (int mf = 0; mf < 2; mf++) {
#pragma unroll
        for (int nf = 0; nf < 4; nf++) {
            int row0 = bm + warp_m + mf * 16 + (lane >> 2);
            int col0 = bn + warp_n + nf * 8 + (lane & 3) * 2;
#pragma unroll
            for (int h = 0; h < 2; h++) {
                int row = row0 + h * 8;
                if (row >= M) continue;
                float v0 = acc[mf][nf][h * 2 + 0];
                float v1 = acc[mf][nf][h * 2 + 1];
                if (Asplit) {
                    v0 += bias0[col0]; v1 += bias0[col0 + 1];
                    if (relu) { v0 = fmaxf(v0, 0.f); v1 = fmaxf(v1, 0.f); }
                    *(uint32_t*)(Asplit + (size_t)row * ldc + col0) = pack_h2(v0, v1);
                } else {
                    bool second = col0 >= split;
                    const float* bs = second ? bias1 : bias0;
                    float* dst = second ? C1 : C0;
                    int cc = second ? col0 - split : col0;
                    v0 += bs[cc]; v1 += bs[cc + 1];
                    if (relu) { v0 = fmaxf(v0, 0.f); v1 = fmaxf(v1, 0.f); }
                    *(float2*)(dst + (size_t)row * ldc + cc) = make_float2(v0, v1);
                }
            }
        }
    }
}

// =============== host orchestration ===============
#define SMEM_BYTES (NSTAGE * (A_ELEMS + B_ELEMS) * 2)

static void launch_gemm(const __half* A, const __half* B,
                        const float* bias0, const float* bias1,
                        float* C0, float* C1, __half* Asplit,
                        int Kbig, int Kb, int N, int ldc, int relu, int split) {
    dim3 grid(N / 128, (NN + 63) / 64);
    k_mgemm<<<grid, 256, SMEM_BYTES>>>(A, B, bias0, bias1, C0, C1, Asplit,
                                       NN, Kbig, Kb, ldc, relu, split);
}

extern "C" void kernel_launch(void* const* d_in, const int* in_sizes, int n_in,
                              void* d_out, int out_size) {
    const float* v    = (const float*)d_in[0];
    const int* ei     = (const int*)d_in[1];
    const float* W1   = (const float*)d_in[2];
    const float* b1   = (const float*)d_in[3];
    const float* W2   = (const float*)d_in[4];
    const float* b2   = (const float*)d_in[5];
    const float* W3   = (const float*)d_in[6];
    const float* b3   = (const float*)d_in[7];
    const float* Wmu  = (const float*)d_in[8];
    const float* bmu  = (const float*)d_in[9];
    const float* Wstd = (const float*)d_in[10];
    const float* bstd = (const float*)d_in[11];
    float* out = (float*)d_out;

    static bool init_done = false;
    static cudaStream_t s2;
    static cudaEvent_t evFork, evDone;
    if (!init_done) {
        cudaFuncSetAttribute(k_mgemm, cudaFuncAttributeMaxDynamicSharedMemorySize, SMEM_BYTES);
        cudaStreamCreateWithFlags(&s2, cudaStreamNonBlocking);
        cudaEventCreateWithFlags(&evFork, cudaEventDisableTiming);
        cudaEventCreateWithFlags(&evDone, cudaEventDisableTiming);
        init_done = true;
    }

    float *deg, *dis, *tx1, *csr_w;
    int *cnt, *rowptr, *cursor, *csr_src;
    __half *xh1, *xh, *tx1h, *Abig, *Ah, *B1, *B2, *B3, *Bh;
    cudaGetSymbolAddress((void**)&deg,     g_deg);
    cudaGetSymbolAddress((void**)&dis,     g_dis);
    cudaGetSymbolAddress((void**)&cnt,     g_cnt);
    cudaGetSymbolAddress((void**)&rowptr,  g_rowptr);
    cudaGetSymbolAddress((void**)&cursor,  g_cursor);
    cudaGetSymbolAddress((void**)&csr_src, g_csr_src);
    cudaGetSymbolAddress((void**)&csr_w,   g_csr_w);
    cudaGetSymbolAddress((void**)&tx1,     g_tx1);
    cudaGetSymbolAddress((void**)&xh1,     g_xh1);
    cudaGetSymbolAddress((void**)&xh,      g_xh);
    cudaGetSymbolAddress((void**)&tx1h,    g_tx1h);
    cudaGetSymbolAddress((void**)&Abig,    g_Abig);
    cudaGetSymbolAddress((void**)&Ah,      g_Ah);
    cudaGetSymbolAddress((void**)&B1,      g_B1);
    cudaGetSymbolAddress((void**)&B2,      g_B2);
    cudaGetSymbolAddress((void**)&B3,      g_B3);
    cudaGetSymbolAddress((void**)&Bh,      g_Bh);

    // fork side stream: single mega weight-conversion kernel
    cudaEventRecord(evFork, 0);
    cudaStreamWaitEvent(s2, evFork, 0);
    k_wconv_all<<<3136, 256, 0, s2>>>(W1, W2, W3, Wmu, Wstd, B1, B2, B3, Bh);
    cudaEventRecord(evDone, s2);

    // preprocessing (deg/cnt are zero at entry; k_scan re-zeroes them)
    k_counts<<<(NE + 255) / 256, 256>>>(ei, deg, cnt);
    k_scan<<<1, 1024>>>(cnt, rowptr, cursor, deg, dis);
    k_scatter<<<(NE + 255) / 256, 256>>>(ei, dis, cursor, csr_src, csr_w);

    const int pgn = (NN + 3) / 4;

    // L1: fp32 props on v (2-term A), GEMM -> fp16 hi xh1
    k_gprop1<<<pgn, 128>>>(rowptr, csr_src, csr_w, v, tx1, Abig);
    k_gprop2<<<pgn, 128>>>(rowptr, csr_src, csr_w, v, tx1, Abig);
    cudaStreamWaitEvent(0, evDone, 0);
    launch_gemm(Abig, B1, b1, b1, nullptr, nullptr, xh1, 768, 384, 128, 128, 1, 128);

    // L2: fp16 props on xh1 (2-term A, lo(tx0)=0), GEMM -> fp16 hi xh
    k_gprop1h128<<<pgn, 128>>>(rowptr, csr_src, csr_w, xh1, tx1h, Abig);
    k_gprop2h128<<<pgn, 128>>>(rowptr, csr_src, csr_w, xh1, tx1h, Abig);
    launch_gemm(Abig, B2, b2, b2, nullptr, nullptr, xh, 768, 384, 256, 256, 1, 256);

    // L3: fp16 props on xh (hi-only A), GEMM -> fp16 hi Ah
    k_gprop1h<<<pgn, 128>>>(rowptr, csr_src, csr_w, xh, tx1h, Abig);
    k_gprop2h<<<pgn, 128>>>(rowptr, csr_src, csr_w, xh, tx1h, Abig);
    launch_gemm(Abig, B3, b3, b3, nullptr, nullptr, Ah, 768, 768, 512, 512, 1, 512);

    // fused heads: one N=512 GEMM on Ah (K=512), split mu|std
    launch_gemm(Ah, Bh, bmu, bstd, out, out + (size_t)NN * 256, nullptr,
                512, 512, 512, 256, 0, 256);

    (void)in_sizes; (void)n_in; (void)out_size;
}

// round 17
// speedup vs baseline: 1.0328x; 1.0328x over previous
#include <cuda_runtime.h>
#include <cuda_fp16.h>
#include <math.h>
#include <stdint.h>

#define NN 10000
#define NE 160000

// ---- scratch (static device globals; zero-initialized at module load) ----
__device__ float g_deg[NN];
__device__ float g_dis[NN];
__device__ int   g_cnt[NN];
__device__ int   g_rowptr[NN + 1];
__device__ int   g_cursor[NN];
__device__ int   g_csr_src[NE];
__device__ float g_csr_w[NE];
__device__ float g_tx1[NN * 128];
__device__ __half g_xh1[NN * 128];
__device__ __half g_xh[NN * 256];
__device__ __half g_tx1h[NN * 256];
__device__ __half g_Abig[NN * 1536];
__device__ __half g_Ah[NN * 512];
__device__ __half g_B1[128 * 384];
__device__ __half g_B2[256 * 384];
__device__ __half g_B3[512 * 768];
__device__ __half g_Bh[512 * 512];

__device__ __forceinline__ uint32_t smem_u32(const void* p) {
    uint32_t a;
    asm("{ .reg .u64 t; cvta.to.shared.u64 t, %1; cvt.u32.u64 %0, t; }" : "=r"(a) : "l"(p));
    return a;
}
__device__ __forceinline__ uint32_t pack_h2(float a, float b) {
    __half2 t = __floats2half2_rn(a, b);
    return *(uint32_t*)&t;
}
__device__ __forceinline__ void pdl_wait() {
    cudaGridDependencySynchronize();   // no-op when launched without PDL dependency
}

// =============== graph preprocessing ===============
__global__ void k_counts(const int* __restrict__ ei, float* __restrict__ deg,
                         int* __restrict__ cnt) {
    int e = blockIdx.x * blockDim.x + threadIdx.x;
    if (e < NE) {
        atomicAdd(&deg[ei[e]], 1.f);
        atomicAdd(&cnt[ei[NE + e]], 1);
    }
}
__global__ void k_scan(int* __restrict__ cnt, int* __restrict__ rowptr,
                       int* __restrict__ cursor, float* __restrict__ deg,
                       float* __restrict__ dis) {
    pdl_wait();
    __shared__ int wsum[32];
    __shared__ int carry_s;
    int tid = threadIdx.x, lane = tid & 31, wid = tid >> 5;
    if (tid == 0) { carry_s = 0; rowptr[0] = 0; }
    __syncthreads();
    for (int base = 0; base < NN; base += 1024) {
        int i = base + tid;
        int v = 0;
        if (i < NN) {
            float d = deg[i];
            dis[i] = (d > 0.f) ? rsqrtf(d) : 0.f;
            deg[i] = 0.f;
            v = cnt[i];
            cnt[i] = 0;
        }
        int x = v;
#pragma unroll
        for (int o = 1; o < 32; o <<= 1) {
            int t = __shfl_up_sync(0xffffffffu, x, o);
            if (lane >= o) x += t;
        }
        if (lane == 31) wsum[wid] = x;
        __syncthreads();
        if (wid == 0) {
            int s = wsum[lane];
#pragma unroll
            for (int o = 1; o < 32; o <<= 1) {
                int t = __shfl_up_sync(0xffffffffu, s, o);
                if (lane >= o) s += t;
            }
            wsum[lane] = s;
        }
        __syncthreads();
        int inc = carry_s + ((wid > 0) ? wsum[wid - 1] : 0) + x;
        if (i < NN) { rowptr[i + 1] = inc; cursor[i] = inc - v; }
        __syncthreads();
        if (tid == 1023) carry_s = inc;
        __syncthreads();
    }
}
__global__ void k_scatter(const int* __restrict__ ei, const float* __restrict__ dis,
                          int* __restrict__ cursor, int* __restrict__ csr_src,
                          float* __restrict__ csr_w) {
    pdl_wait();
    int e = blockIdx.x * blockDim.x + threadIdx.x;
    if (e < NE) {
        int r = ei[e];
        int c = ei[NE + e];
        int p = atomicAdd(&cursor[c], 1);
        csr_src[p] = r;
        csr_w[p] = -dis[r] * dis[c];
    }
}

// =============== fp32-gather props (L1, Fin=128, 2-term writes) ===============
__device__ __forceinline__ void split_write4(__half* row, int Fin, int pos, float4 v) {
    float hx = __half2float(__float2half_rn(v.x));
    float hy = __half2float(__float2half_rn(v.y));
    float hz = __half2float(__float2half_rn(v.z));
    float hw = __half2float(__float2half_rn(v.w));
    uint2 hi = make_uint2(pack_h2(v.x, v.y), pack_h2(v.z, v.w));
    uint2 lo = make_uint2(pack_h2(v.x - hx, v.y - hy), pack_h2(v.z - hz, v.w - hw));
    *(uint2*)(row + pos) = hi;
    *(uint2*)(row + 3 * Fin + pos) = lo;
}
__device__ __forceinline__ float4 gather_acc(
    const int* __restrict__ csr_src, const float* __restrict__ csr_w,
    const float* __restrict__ base, int Fin, int f, int s, int e, int lane)
{
    float4 a0 = make_float4(0.f, 0.f, 0.f, 0.f);
    float4 a1 = a0, a2 = a0, a3 = a0;
    for (int j0 = s; j0 < e; j0 += 32) {
        int j = j0 + lane;
        int es = 0; float ew = 0.f;
        if (j < e) { es = csr_src[j]; ew = csr_w[j]; }
        int m = min(32, e - j0);
        int t = 0;
        for (; t + 4 <= m; t += 4) {
            int s0 = __shfl_sync(0xffffffffu, es, t + 0);
            int s1 = __shfl_sync(0xffffffffu, es, t + 1);
            int s2 = __shfl_sync(0xffffffffu, es, t + 2);
            int s3 = __shfl_sync(0xffffffffu, es, t + 3);
            float w0 = __shfl_sync(0xffffffffu, ew, t + 0);
            float w1 = __shfl_sync(0xffffffffu, ew, t + 1);
            float w2 = __shfl_sync(0xffffffffu, ew, t + 2);
            float w3 = __shfl_sync(0xffffffffu, ew, t + 3);
            float4 v0 = *(const float4*)(base + (size_t)s0 * Fin + f);
            float4 v1 = *(const float4*)(base + (size_t)s1 * Fin + f);
            float4 v2 = *(const float4*)(base + (size_t)s2 * Fin + f);
            float4 v3 = *(const float4*)(base + (size_t)s3 * Fin + f);
            a0.x += w0 * v0.x; a0.y += w0 * v0.y; a0.z += w0 * v0.z; a0.w += w0 * v0.w;
            a1.x += w1 * v1.x; a1.y += w1 * v1.y; a1.z += w1 * v1.z; a1.w += w1 * v1.w;
            a2.x += w2 * v2.x; a2.y += w2 * v2.y; a2.z += w2 * v2.z; a2.w += w2 * v2.w;
            a3.x += w3 * v3.x; a3.y += w3 * v3.y; a3.z += w3 * v3.z; a3.w += w3 * v3.w;
        }
        for (; t < m; t++) {
            int s0 = __shfl_sync(0xffffffffu, es, t);
            float w0 = __shfl_sync(0xffffffffu, ew, t);
            float4 v0 = *(const float4*)(base + (size_t)s0 * Fin + f);
            a0.x += w0 * v0.x; a0.y += w0 * v0.y; a0.z += w0 * v0.z; a0.w += w0 * v0.w;
        }
    }
    a0.x += a1.x + a2.x + a3.x;
    a0.y += a1.y + a2.y + a3.y;
    a0.z += a1.z + a2.z + a3.z;
    a0.w += a1.w + a2.w + a3.w;
    return a0;
}
__global__ __launch_bounds__(128) void k_gprop1(
    const int* __restrict__ rowptr, const int* __restrict__ csr_src,
    const float* __restrict__ csr_w, const float* __restrict__ x,
    float* __restrict__ tx1, __half* __restrict__ Abig)
{
    pdl_wait();
    const int Fin = 128;
    int warp = threadIdx.x >> 5, lane = threadIdx.x & 31;
    int n = blockIdx.x * 4 + warp;
    if (n >= NN) return;
    int f = lane * 4;
    float4 acc = gather_acc(csr_src, csr_w, x, Fin, f, rowptr[n], rowptr[n + 1], lane);
    float4 x0 = *(const float4*)(x + (size_t)n * Fin + f);
    __half* row = Abig + (size_t)n * 6 * Fin;
    split_write4(row, Fin, f, x0);
    split_write4(row, Fin, Fin + f, acc);
    *(float4*)(tx1 + (size_t)n * Fin + f) = acc;
}
__global__ __launch_bounds__(128) void k_gprop2(
    const int* __restrict__ rowptr, const int* __restrict__ csr_src,
    const float* __restrict__ csr_w, const float* __restrict__ x,
    const float* __restrict__ tx1, __half* __restrict__ Abig)
{
    pdl_wait();
    const int Fin = 128;
    int warp = threadIdx.x >> 5, lane = threadIdx.x & 31;
    int n = blockIdx.x * 4 + warp;
    if (n >= NN) return;
    int f = lane * 4;
    float4 acc = gather_acc(csr_src, csr_w, tx1, Fin, f, rowptr[n], rowptr[n + 1], lane);
    float4 x0 = *(const float4*)(x + (size_t)n * Fin + f);
    float4 t2 = make_float4(2.f * acc.x - x0.x, 2.f * acc.y - x0.y,
                            2.f * acc.z - x0.z, 2.f * acc.w - x0.w);
    __half* row = Abig + (size_t)n * 6 * Fin;
    split_write4(row, Fin, 2 * Fin + f, t2);
}

// =============== fp16-gather props, Fin=128 (L2, 2-term A writes) ===============
__device__ __forceinline__ void h4_acc(float* acc, uint2 v, float w) {
    const __half2* h = (const __half2*)&v;
    float2 a = __half22float2(h[0]);
    float2 b = __half22float2(h[1]);
    acc[0] += w * a.x; acc[1] += w * a.y;
    acc[2] += w * b.x; acc[3] += w * b.y;
}
__device__ __forceinline__ void gather_acc_h128(
    float* acc, const int* __restrict__ csr_src, const float* __restrict__ csr_w,
    const __half* __restrict__ base, int f, int s, int e, int lane)
{
    for (int j0 = s; j0 < e; j0 += 32) {
        int j = j0 + lane;
        int es = 0; float ew = 0.f;
        if (j < e) { es = csr_src[j]; ew = csr_w[j]; }
        int m = min(32, e - j0);
        int t = 0;
        for (; t + 4 <= m; t += 4) {
            int s0 = __shfl_sync(0xffffffffu, es, t + 0);
            int s1 = __shfl_sync(0xffffffffu, es, t + 1);
            int s2 = __shfl_sync(0xffffffffu, es, t + 2);
            int s3 = __shfl_sync(0xffffffffu, es, t + 3);
            float w0 = __shfl_sync(0xffffffffu, ew, t + 0);
            float w1 = __shfl_sync(0xffffffffu, ew, t + 1);
            float w2 = __shfl_sync(0xffffffffu, ew, t + 2);
            float w3 = __shfl_sync(0xffffffffu, ew, t + 3);
            uint2 v0 = *(const uint2*)(base + (size_t)s0 * 128 + f);
            uint2 v1 = *(const uint2*)(base + (size_t)s1 * 128 + f);
            uint2 v2 = *(const uint2*)(base + (size_t)s2 * 128 + f);
            uint2 v3 = *(const uint2*)(base + (size_t)s3 * 128 + f);
            h4_acc(acc, v0, w0);
            h4_acc(acc, v1, w1);
            h4_acc(acc, v2, w2);
            h4_acc(acc, v3, w3);
        }
        for (; t < m; t++) {
            int s0 = __shfl_sync(0xffffffffu, es, t);
            float w0 = __shfl_sync(0xffffffffu, ew, t);
            uint2 v0 = *(const uint2*)(base + (size_t)s0 * 128 + f);
            h4_acc(acc, v0, w0);
        }
    }
}
__device__ __forceinline__ void split_pair(float a, float b, uint32_t& hi, uint32_t& lo) {
    float ha = __half2float(__float2half_rn(a));
    float hb = __half2float(__float2half_rn(b));
    hi = pack_h2(a, b);
    lo = pack_h2(a - ha, b - hb);
}
__global__ __launch_bounds__(128) void k_gprop1h128(
    const int* __restrict__ rowptr, const int* __restrict__ csr_src,
    const float* __restrict__ csr_w, const __half* __restrict__ xh,
    __half* __restrict__ tx1h, __half* __restrict__ Abig)
{
    pdl_wait();
    int warp = threadIdx.x >> 5, lane = threadIdx.x & 31;
    int n = blockIdx.x * 4 + warp;
    if (n >= NN) return;
    int f = lane * 4;
    float acc[4] = {0.f, 0.f, 0.f, 0.f};
    gather_acc_h128(acc, csr_src, csr_w, xh, f, rowptr[n], rowptr[n + 1], lane);
    uint2 x0 = *(const uint2*)(xh + (size_t)n * 128 + f);
    __half* row = Abig + (size_t)n * 768;
    *(uint2*)(row + f) = x0;
    *(uint2*)(row + 384 + f) = make_uint2(0u, 0u);
    uint2 hi, lo;
    split_pair(acc[0], acc[1], hi.x, lo.x);
    split_pair(acc[2], acc[3], hi.y, lo.y);
    *(uint2*)(row + 128 + f) = hi;
    *(uint2*)(row + 512 + f) = lo;
    *(uint2*)(tx1h + (size_t)n * 128 + f) = hi;
}
__global__ __launch_bounds__(128) void k_gprop2h128(
    const int* __restrict__ rowptr, const int* __restrict__ csr_src,
    const float* __restrict__ csr_w, const __half* __restrict__ xh,
    const __half* __restrict__ tx1h, __half* __restrict__ Abig)
{
    pdl_wait();
    int warp = threadIdx.x >> 5, lane = threadIdx.x & 31;
    int n = blockIdx.x * 4 + warp;
    if (n >= NN) return;
    int f = lane * 4;
    float acc[4] = {0.f, 0.f, 0.f, 0.f};
    gather_acc_h128(acc, csr_src, csr_w, tx1h, f, rowptr[n], rowptr[n + 1], lane);
    uint2 x0 = *(const uint2*)(xh + (size_t)n * 128 + f);
    const __half2* xh2 = (const __half2*)&x0;
    float2 fa = __half22float2(xh2[0]);
    float2 fb = __half22float2(xh2[1]);
    float t2[4] = {2.f * acc[0] - fa.x, 2.f * acc[1] - fa.y,
                   2.f * acc[2] - fb.x, 2.f * acc[3] - fb.y};
    __half* row = Abig + (size_t)n * 768;
    uint2 hi, lo;
    split_pair(t2[0], t2[1], hi.x, lo.x);
    split_pair(t2[2], t2[3], hi.y, lo.y);
    *(uint2*)(row + 256 + f) = hi;
    *(uint2*)(row + 640 + f) = lo;
}

// =============== fp16-gather props, Fin=256 (L3, hi-only writes) ===============
__device__ __forceinline__ void h8_acc(float* acc, uint4 v, float w) {
    const __half2* h = (const __half2*)&v;
#pragma unroll
    for (int q = 0; q < 4; q++) {
        float2 fv = __half22float2(h[q]);
        acc[2 * q]     += w * fv.x;
        acc[2 * q + 1] += w * fv.y;
    }
}
__device__ __forceinline__ void gather_acc_h(
    float* acc, const int* __restrict__ csr_src, const float* __restrict__ csr_w,
    const __half* __restrict__ base, int f, int s, int e, int lane)
{
    for (int j0 = s; j0 < e; j0 += 32) {
        int j = j0 + lane;
        int es = 0; float ew = 0.f;
        if (j < e) { es = csr_src[j]; ew = csr_w[j]; }
        int m = min(32, e - j0);
        int t = 0;
        for (; t + 4 <= m; t += 4) {
            int s0 = __shfl_sync(0xffffffffu, es, t + 0);
            int s1 = __shfl_sync(0xffffffffu, es, t + 1);
            int s2 = __shfl_sync(0xffffffffu, es, t + 2);
            int s3 = __shfl_sync(0xffffffffu, es, t + 3);
            float w0 = __shfl_sync(0xffffffffu, ew, t + 0);
            float w1 = __shfl_sync(0xffffffffu, ew, t + 1);
            float w2 = __shfl_sync(0xffffffffu, ew, t + 2);
            float w3 = __shfl_sync(0xffffffffu, ew, t + 3);
            uint4 v0 = *(const uint4*)(base + (size_t)s0 * 256 + f);
            uint4 v1 = *(const uint4*)(base + (size_t)s1 * 256 + f);
            uint4 v2 = *(const uint4*)(base + (size_t)s2 * 256 + f);
            uint4 v3 = *(const uint4*)(base + (size_t)s3 * 256 + f);
            h8_acc(acc, v0, w0);
            h8_acc(acc, v1, w1);
            h8_acc(acc, v2, w2);
            h8_acc(acc, v3, w3);
        }
        for (; t < m; t++) {
            int s0 = __shfl_sync(0xffffffffu, es, t);
            float w0 = __shfl_sync(0xffffffffu, ew, t);
            uint4 v0 = *(const uint4*)(base + (size_t)s0 * 256 + f);
            h8_acc(acc, v0, w0);
        }
    }
}
__device__ __forceinline__ uint4 pack_h8(const float* a) {
    uint4 r;
    r.x = pack_h2(a[0], a[1]);
    r.y = pack_h2(a[2], a[3]);
    r.z = pack_h2(a[4], a[5]);
    r.w = pack_h2(a[6], a[7]);
    return r;
}
__global__ __launch_bounds__(128) void k_gprop1h(
    const int* __restrict__ rowptr, const int* __restrict__ csr_src,
    const float* __restrict__ csr_w, const __half* __restrict__ xh,
    __half* __restrict__ tx1h, __half* __restrict__ Abig)
{
    pdl_wait();
    int warp = threadIdx.x >> 5, lane = threadIdx.x & 31;
    int n = blockIdx.x * 4 + warp;
    if (n >= NN) return;
    int f = lane * 8;
    float acc[8] = {0.f, 0.f, 0.f, 0.f, 0.f, 0.f, 0.f, 0.f};
    gather_acc_h(acc, csr_src, csr_w, xh, f, rowptr[n], rowptr[n + 1], lane);
    uint4 x0 = *(const uint4*)(xh + (size_t)n * 256 + f);
    __half* row = Abig + (size_t)n * 768;
    *(uint4*)(row + f) = x0;
    uint4 p = pack_h8(acc);
    *(uint4*)(row + 256 + f) = p;
    *(uint4*)(tx1h + (size_t)n * 256 + f) = p;
}
__global__ __launch_bounds__(128) void k_gprop2h(
    const int* __restrict__ rowptr, const int* __restrict__ csr_src,
    const float* __restrict__ csr_w, const __half* __restrict__ xh,
    const __half* __restrict__ tx1h, __half* __restrict__ Abig)
{
    pdl_wait();
    int warp = threadIdx.x >> 5, lane = threadIdx.x & 31;
    int n = blockIdx.x * 4 + warp;
    if (n >= NN) return;
    int f = lane * 8;
    float acc[8] = {0.f, 0.f, 0.f, 0.f, 0.f, 0.f, 0.f, 0.f};
    gather_acc_h(acc, csr_src, csr_w, tx1h, f, rowptr[n], rowptr[n + 1], lane);
    uint4 x0 = *(const uint4*)(xh + (size_t)n * 256 + f);
    const __half2* xh2 = (const __half2*)&x0;
    float t2[8];
#pragma unroll
    for (int q = 0; q < 4; q++) {
        float2 fv = __half22float2(xh2[q]);
        t2[2 * q]     = 2.f * acc[2 * q]     - fv.x;
        t2[2 * q + 1] = 2.f * acc[2 * q + 1] - fv.y;
    }
    *(uint4*)(Abig + (size_t)n * 768 + 512 + f) = pack_h8(t2);
}

// =============== single mega weight-conversion kernel (all 5 matrices) ===============
__global__ void k_wconv_all(
    const float* __restrict__ W1, const float* __restrict__ W2,
    const float* __restrict__ W3, const float* __restrict__ Wmu,
    const float* __restrict__ Wstd,
    __half* __restrict__ B1, __half* __restrict__ B2,
    __half* __restrict__ B3, __half* __restrict__ Bh)
{
    int b = blockIdx.x;
    const float* W; __half* B; int K, N;
    if (b < 192)       { W = W1;   B = B1;                        K = 384; N = 128; }
    else if (b < 576)  { W = W2;   B = B2;                        K = 384; N = 256; b -= 192; }
    else if (b < 2112) { W = W3;   B = B3;                        K = 768; N = 512; b -= 576; }
    else if (b < 2624) { W = Wmu;  B = Bh;                        K = 512; N = 256; b -= 2112; }
    else               { W = Wstd; B = Bh + (size_t)256 * 512;    K = 512; N = 256; b -= 2624; }
    int i = b * 256 + threadIdx.x;
    if (i < K * N) {
        int k = i / N;
        int n = i - k * N;
        B[(size_t)n * K + k] = __float2half_rn(W[i]);
    }
}

// =============== mma.sync fp16 GEMM, 64x128 tile, BK=64, 4-stage cp.async ===============
#define LDT 72
#define NSTAGE 4
#define A_ELEMS (64 * LDT)
#define B_ELEMS (128 * LDT)

__device__ __forceinline__ void ldm_x4(uint32_t& r0, uint32_t& r1, uint32_t& r2, uint32_t& r3,
                                       uint32_t a) {
    asm volatile("ldmatrix.sync.aligned.m8n8.x4.shared.b16 {%0,%1,%2,%3}, [%4];"
                 : "=r"(r0), "=r"(r1), "=r"(r2), "=r"(r3) : "r"(a));
}
__device__ __forceinline__ void mma_f16(float* c, const uint32_t* a, const uint32_t* b) {
    asm volatile(
        "mma.sync.aligned.m16n8k16.row.col.f32.f16.f16.f32 "
        "{%0,%1,%2,%3}, {%4,%5,%6,%7}, {%8,%9}, {%0,%1,%2,%3};"
        : "+f"(c[0]), "+f"(c[1]), "+f"(c[2]), "+f"(c[3])
        : "r"(a[0]), "r"(a[1]), "r"(a[2]), "r"(a[3]), "r"(b[0]), "r"(b[1]));
}
__device__ __forceinline__ void cp16(uint32_t dst, const void* src, int pred16) {
    asm volatile("cp.async.cg.shared.global [%0], [%1], 16, %2;"
                 :: "r"(dst), "l"(src), "r"(pred16) : "memory");
}

__global__ __launch_bounds__(256) void k_mgemm(
    const __half* __restrict__ A, const __half* __restrict__ B,
    const float* __restrict__ bias0, const float* __restrict__ bias1,
    float* __restrict__ C0, float* __restrict__ C1,
    __half* __restrict__ Asplit,
    int M, int Kbig, int Kb, int ldc, int relu, int split)
{
    pdl_wait();
    extern __shared__ __align__(16) __half smp[];
    __half* sAp = smp;
    __half* sBp = smp + NSTAGE * A_ELEMS;

    const int tid = threadIdx.x;
    const int wid = tid >> 5;
    const int lane = tid & 31;
    const int bm = blockIdx.y * 64;
    const int bn = blockIdx.x * 128;
    const int warp_m = (wid & 1) * 32;
    const int warp_n = (wid >> 1) * 32;

    float acc[2][4][4];
#pragma unroll
    for (int i = 0; i < 2; i++)
#pragma unroll
        for (int j = 0; j < 4; j++)
#pragma unroll
            for (int q = 0; q < 4; q++) acc[i][j][q] = 0.f;

    uint32_t sA_u[NSTAGE], sB_u[NSTAGE];
#pragma unroll
    for (int s = 0; s < NSTAGE; s++) {
        sA_u[s] = smem_u32(sAp + s * A_ELEMS);
        sB_u[s] = smem_u32(sBp + s * B_ELEMS);
    }
    const int niter = Kbig >> 6;

    auto issue = [&](int stage, int k0) {
#pragma unroll
        for (int h = 0; h < 2; h++) {
            int c = tid + h * 256;
            int r = c >> 3, col = c & 7;
            cp16(sA_u[stage] + (r * LDT + col * 8) * 2,
                 A + (size_t)(bm + r) * Kbig + k0 + col * 8, (bm + r) < M ? 16 : 0);
        }
        int kb = (k0 < Kb) ? k0 : k0 - Kb;
#pragma unroll
        for (int h = 0; h < 4; h++) {
            int c = tid + h * 256;
            int r = c >> 3, col = c & 7;
            cp16(sB_u[stage] + (r * LDT + col * 8) * 2,
                 B + (size_t)(bn + r) * Kb + kb + col * 8, 16);
        }
        asm volatile("cp.async.commit_group;" ::: "memory");
    };

    issue(0, 0);
    issue(1, 64);
    issue(2, 128);

    int stage = 0;
    for (int it = 0; it < niter; it++) {
        const int ahead = niter - 1 - it;
        if (ahead >= 2)      asm volatile("cp.async.wait_group 2;" ::: "memory");
        else if (ahead == 1) asm volatile("cp.async.wait_group 1;" ::: "memory");
        else                 asm volatile("cp.async.wait_group 0;" ::: "memory");
        __syncthreads();

        if (it + 3 < niter) {
            int ns = stage + 3; if (ns >= NSTAGE) ns -= NSTAGE;
            issue(ns, (it + 3) << 6);
        }

#pragma unroll
        for (int ks = 0; ks < 4; ks++) {
            uint32_t af[2][4];
            uint32_t bf[4][2];
#pragma unroll
            for (int mf = 0; mf < 2; mf++) {
                uint32_t addr = sA_u[stage] +
                    ((warp_m + mf * 16 + (lane & 15)) * LDT + ks * 16 + (lane >> 4) * 8) * 2;
                ldm_x4(af[mf][0], af[mf][1], af[mf][2], af[mf][3], addr);
            }
#pragma unroll
            for (int nfp = 0; nfp < 2; nfp++) {
                uint32_t addr = sB_u[stage] +
                    ((warp_n + nfp * 16 + (lane & 15)) * LDT + ks * 16 + (lane >> 4) * 8) * 2;
                uint32_t r0, r1, r2, r3;
                ldm_x4(r0, r1, r2, r3, addr);
                bf[nfp * 2 + 0][0] = r0; bf[nfp * 2 + 1][0] = r1;
                bf[nfp * 2 + 0][1] = r2; bf[nfp * 2 + 1][1] = r3;
            }
#pragma unroll
            for (int mf = 0; mf < 2; mf++)
#pragma unroll
                for (int nf = 0; nf < 4; nf++)
                    mma_f16(acc[mf][nf], af[mf], bf[nf]);
        }
        if (++stage == NSTAGE) stage = 0;
    }

    // epilogue
#pragma unroll
    for (int mf = 0; mf < 2; mf++) {
#pragma unroll
        for (int nf = 0; nf < 4; nf++) {
            int row0 = bm + warp_m + mf * 16 + (lane >> 2);
            int col0 = bn + warp_n + nf * 8 + (lane & 3) * 2;
#pragma unroll
            for (int h = 0; h < 2; h++) {
                int row = row0 + h * 8;
                if (row >= M) continue;
                float v0 = acc[mf][nf][h * 2 + 0];
                float v1 = acc[mf][nf][h * 2 + 1];
                if (Asplit) {
                    v0 += bias0[col0]; v1 += bias0[col0 + 1];
                    if (relu) { v0 = fmaxf(v0, 0.f); v1 = fmaxf(v1, 0.f); }
                    *(uint32_t*)(Asplit + (size_t)row * ldc + col0) = pack_h2(v0, v1);
                } else {
                    bool second = col0 >= split;
                    const float* bs = second ? bias1 : bias0;
                    float* dst = second ? C1 : C0;
                    int cc = second ? col0 - split : col0;
                    v0 += bs[cc]; v1 += bs[cc + 1];
                    if (relu) { v0 = fmaxf(v0, 0.f); v1 = fmaxf(v1, 0.f); }
                    *(float2*)(dst + (size_t)row * ldc + cc) = make_float2(v0, v1);
                }
            }
        }
    }
}

// =============== host orchestration ===============
#define SMEM_BYTES (NSTAGE * (A_ELEMS + B_ELEMS) * 2)

template <typename KFn, typename... Args>
static void launch_pdl(KFn kern, dim3 grid, dim3 block, size_t smem, Args... args) {
    cudaLaunchConfig_t cfg = {};
    cfg.gridDim = grid;
    cfg.blockDim = block;
    cfg.dynamicSmemBytes = smem;
    cfg.stream = 0;
    cudaLaunchAttribute attr[1];
    attr[0].id = cudaLaunchAttributeProgrammaticStreamSerialization;
    attr[0].val.programmaticStreamSerializationAllowed = 1;
    cfg.attrs = attr;
    cfg.numAttrs = 1;
    cudaLaunchKernelEx(&cfg, kern, args...);
}

static void gemm_pdl(const __half* A, const __half* B,
                     const float* bias0, const float* bias1,
                     float* C0, float* C1, __half* Asplit,
                     int Kbig, int Kb, int N, int ldc, int relu, int split, bool pdl) {
    dim3 grid(N / 128, (NN + 63) / 64);
    if (pdl) {
        launch_pdl(k_mgemm, grid, dim3(256), (size_t)SMEM_BYTES,
                   A, B, bias0, bias1, C0, C1, Asplit, (int)NN, Kbig, Kb, ldc, relu, split);
    } else {
        k_mgemm<<<grid, 256, SMEM_BYTES>>>(A, B, bias0, bias1, C0, C1, Asplit,
                                           NN, Kbig, Kb, ldc, relu, split);
    }
}

extern "C" void kernel_launch(void* const* d_in, const int* in_sizes, int n_in,
                              void* d_out, int out_size) {
    const float* v    = (const float*)d_in[0];
    const int* ei     = (const int*)d_in[1];
    const float* W1   = (const float*)d_in[2];
    const float* b1   = (const float*)d_in[3];
    const float* W2   = (const float*)d_in[4];
    const float* b2   = (const float*)d_in[5];
    const float* W3   = (const float*)d_in[6];
    const float* b3   = (const float*)d_in[7];
    const float* Wmu  = (const float*)d_in[8];
    const float* bmu  = (const float*)d_in[9];
    const float* Wstd = (const float*)d_in[10];
    const float* bstd = (const float*)d_in[11];
    float* out = (float*)d_out;

    static bool init_done = false;
    static cudaStream_t s2;
    static cudaEvent_t evFork, evDone;
    if (!init_done) {
        cudaFuncSetAttribute(k_mgemm, cudaFuncAttributeMaxDynamicSharedMemorySize, SMEM_BYTES);
        cudaStreamCreateWithFlags(&s2, cudaStreamNonBlocking);
        cudaEventCreateWithFlags(&evFork, cudaEventDisableTiming);
        cudaEventCreateWithFlags(&evDone, cudaEventDisableTiming);
        init_done = true;
    }

    float *deg, *dis, *tx1, *csr_w;
    int *cnt, *rowptr, *cursor, *csr_src;
    __half *xh1, *xh, *tx1h, *Abig, *Ah, *B1, *B2, *B3, *Bh;
    cudaGetSymbolAddress((void**)&deg,     g_deg);
    cudaGetSymbolAddress((void**)&dis,     g_dis);
    cudaGetSymbolAddress((void**)&cnt,     g_cnt);
    cudaGetSymbolAddress((void**)&rowptr,  g_rowptr);
    cudaGetSymbolAddress((void**)&cursor,  g_cursor);
    cudaGetSymbolAddress((void**)&csr_src, g_csr_src);
    cudaGetSymbolAddress((void**)&csr_w,   g_csr_w);
    cudaGetSymbolAddress((void**)&tx1,     g_tx1);
    cudaGetSymbolAddress((void**)&xh1,     g_xh1);
    cudaGetSymbolAddress((void**)&xh,      g_xh);
    cudaGetSymbolAddress((void**)&tx1h,    g_tx1h);
    cudaGetSymbolAddress((void**)&Abig,    g_Abig);
    cudaGetSymbolAddress((void**)&Ah,      g_Ah);
    cudaGetSymbolAddress((void**)&B1,      g_B1);
    cudaGetSymbolAddress((void**)&B2,      g_B2);
    cudaGetSymbolAddress((void**)&B3,      g_B3);
    cudaGetSymbolAddress((void**)&Bh,      g_Bh);

    // fork side stream: single mega weight-conversion kernel
    cudaEventRecord(evFork, 0);
    cudaStreamWaitEvent(s2, evFork, 0);
    k_wconv_all<<<3136, 256, 0, s2>>>(W1, W2, W3, Wmu, Wstd, B1, B2, B3, Bh);
    cudaEventRecord(evDone, s2);

    // preprocessing chain (PDL overlaps launch tails)
    k_counts<<<(NE + 255) / 256, 256>>>(ei, deg, cnt);
    launch_pdl(k_scan, dim3(1), dim3(1024), (size_t)0, cnt, rowptr, cursor, deg, dis);
    launch_pdl(k_scatter, dim3((NE + 255) / 256), dim3(256), (size_t)0,
               ei, dis, cursor, csr_src, csr_w);

    const int pgn = (NN + 3) / 4;

    // L1: fp32 props (2-term A), GEMM -> fp16 hi xh1
    launch_pdl(k_gprop1, dim3(pgn), dim3(128), (size_t)0,
               (const int*)rowptr, (const int*)csr_src, (const float*)csr_w,
               v, tx1, Abig);
    launch_pdl(k_gprop2, dim3(pgn), dim3(128), (size_t)0,
               (const int*)rowptr, (const int*)csr_src, (const float*)csr_w,
               v, (const float*)tx1, Abig);
    cudaStreamWaitEvent(0, evDone, 0);
    gemm_pdl(Abig, B1, b1, b1, nullptr, nullptr, xh1, 768, 384, 128, 128, 1, 128, false);

    // L2: fp16 props on xh1 (2-term A, lo(tx0)=0), GEMM -> fp16 hi xh
    launch_pdl(k_gprop1h128, dim3(pgn), dim3(128), (size_t)0,
               (const int*)rowptr, (const int*)csr_src, (const float*)csr_w,
               (const __half*)xh1, tx1h, Abig);
    launch_pdl(k_gprop2h128, dim3(pgn), dim3(128), (size_t)0,
               (const int*)rowptr, (const int*)csr_src, (const float*)csr_w,
               (const __half*)xh1, (const __half*)tx1h, Abig);
    gemm_pdl(Abig, B2, b2, b2, nullptr, nullptr, xh, 768, 384, 256, 256, 1, 256, true);

    // L3: fp16 props on xh (hi-only A), GEMM -> fp16 hi Ah
    launch_pdl(k_gprop1h, dim3(pgn), dim3(128), (size_t)0,
               (const int*)rowptr, (const int*)csr_src, (const float*)csr_w,
               (const __half*)xh, tx1h, Abig);
    launch_pdl(k_gprop2h, dim3(pgn), dim3(128), (size_t)0,
               (const int*)rowptr, (const int*)csr_src, (const float*)csr_w,
               (const __half*)xh, (const __half*)tx1h, Abig);
    gemm_pdl(Abig, B3, b3, b3, nullptr, nullptr, Ah, 768, 768, 512, 512, 1, 512, true);

    // fused heads: one N=512 GEMM on Ah (K=512), split mu|std
    gemm_pdl(Ah, Bh, bmu, bstd, out, out + (size_t)NN * 256, nullptr,
             512, 512, 512, 256, 0, 256, true);

    (void)in_sizes; (void)n_in; (void)out_size;
}